// round 1
// baseline (speedup 1.0000x reference)
#include <cuda_runtime.h>
#include <cuda_bf16.h>

// Problem constants (fixed by setup_inputs: N=100000, K=8, E=3200000)
#define KDIM 8

static const int MAXN  = 100000;
static const int MAXNK = MAXN * KDIM;

// Scratch accumulators (device globals — no cudaMalloc allowed).
// accQ4[i]  = sum over {self + in-edges} of exp_e * accu_q   (float4: w,x,y,z)
// accDL2[i] = { denom = sum exp_e , sum exp_e * l_src }
__device__ float4 g_accQ4[MAXNK];
__device__ float2 g_accDL2[MAXNK];

// ---------------------------------------------------------------------------
// Kernel 1: seed accumulators with the self term (w=1 -> score = 8*l)
// ---------------------------------------------------------------------------
__global__ void spt_init_kernel(const float* __restrict__ node_levels,
                                const float4* __restrict__ node_q,
                                int NK)
{
    int i = blockIdx.x * blockDim.x + threadIdx.x;
    if (i >= NK) return;
    float l  = node_levels[i];
    float es = __expf(8.0f * l);          // exp_s (shift m omitted; cancels)
    float4 q = node_q[i];
    g_accQ4[i]  = make_float4(es * q.x, es * q.y, es * q.z, es * q.w);
    g_accDL2[i] = make_float2(es, es * l);
}

// ---------------------------------------------------------------------------
// Kernel 2: edge scatter. One thread per (edge, k); 8 consecutive threads
// share one edge -> broadcast edge loads, coalesced 128B node_q gathers.
// ---------------------------------------------------------------------------
__global__ void spt_edge_kernel(const float*  __restrict__ node_levels,
                                const float4* __restrict__ node_q,
                                const float4* __restrict__ edge_rel_q,
                                const float*  __restrict__ edge_w,
                                const int*    __restrict__ edge_src,
                                const int*    __restrict__ edge_dst,
                                long long EK)
{
    long long t = (long long)blockIdx.x * blockDim.x + threadIdx.x;
    if (t >= EK) return;
    int e = (int)(t >> 3);
    int k = (int)(t & 7);

    int   s  = __ldg(edge_src + e);
    int   d  = __ldg(edge_dst + e);
    float w  = __ldg(edge_w + e);
    float4 rq = __ldg(edge_rel_q + e);

    int si = s * KDIM + k;
    float4 qs = __ldg(node_q + si);
    float  l  = __ldg(node_levels + si);

    float ee = __expf(8.0f * w * l);      // exp_e (unshifted)

    // Hamilton product: accu_q = rel_q (*) q_src ; storage order (w,x,y,z)
    float w1 = rq.x, x1 = rq.y, y1 = rq.z, z1 = rq.w;
    float w2 = qs.x, x2 = qs.y, y2 = qs.z, z2 = qs.w;
    float ow = w1*w2 - x1*x2 - y1*y2 - z1*z2;
    float ox = w1*x2 + x1*w2 + y1*z2 - z1*y2;
    float oy = w1*y2 - x1*z2 + y1*w2 + z1*x2;
    float oz = w1*z2 + x1*y2 - y1*x2 + z1*w2;

    int di = d * KDIM + k;

    // Vector reductions: 1x v4 + 1x v2 per (edge,k) instead of 6 scalar atomics
    float4* aq = g_accQ4 + di;
    asm volatile("red.global.add.v4.f32 [%0], {%1, %2, %3, %4};"
                 :: "l"(aq), "f"(ee*ow), "f"(ee*ox), "f"(ee*oy), "f"(ee*oz)
                 : "memory");
    float2* adl = g_accDL2 + di;
    asm volatile("red.global.add.v2.f32 [%0], {%1, %2};"
                 :: "l"(adl), "f"(ee), "f"(ee*l)
                 : "memory");
}

// ---------------------------------------------------------------------------
// Kernel 3: finalize. out_q = normalize(accQ / denom), out_l = accL / denom.
// ---------------------------------------------------------------------------
__global__ void spt_final_kernel(float4* __restrict__ out_q,
                                 float*  __restrict__ out_l,
                                 int NK)
{
    int i = blockIdx.x * blockDim.x + threadIdx.x;
    if (i >= NK) return;
    float2 dl  = g_accDL2[i];
    float  inv = 1.0f / dl.x;
    float4 a   = g_accQ4[i];
    float qw = a.x * inv, qx = a.y * inv, qy = a.z * inv, qz = a.w * inv;
    float nrm = sqrtf(qw*qw + qx*qx + qy*qy + qz*qz);
    float r   = 1.0f / fmaxf(nrm, 1e-12f);
    out_q[i] = make_float4(qw * r, qx * r, qy * r, qz * r);
    out_l[i] = dl.y * inv;
}

// ---------------------------------------------------------------------------
// Launch: inputs in metadata order:
//   0 node_levels [N,K] f32, 1 node_q [N,K,4] f32, 2 edge_rel_q [E,4] f32,
//   3 edge_w [E] f32, 4 edge_src [E] i32, 5 edge_dst [E] i32
// Output: q [N,K,4] flattened, then out_levels [N,K].
// ---------------------------------------------------------------------------
extern "C" void kernel_launch(void* const* d_in, const int* in_sizes, int n_in,
                              void* d_out, int out_size)
{
    const float*  node_levels = (const float*) d_in[0];
    const float4* node_q      = (const float4*)d_in[1];
    const float4* edge_rel_q  = (const float4*)d_in[2];
    const float*  edge_w      = (const float*) d_in[3];
    const int*    edge_src    = (const int*)   d_in[4];
    const int*    edge_dst    = (const int*)   d_in[5];

    int NK = in_sizes[0];                 // N*K
    int E  = in_sizes[3];
    long long EK = (long long)E * KDIM;

    float4* out_q = (float4*)d_out;
    float*  out_l = (float*)d_out + (long long)NK * 4;

    const int TPB = 256;
    int grid_nk = (NK + TPB - 1) / TPB;
    long long grid_ek_ll = (EK + TPB - 1) / TPB;
    int grid_ek = (int)grid_ek_ll;

    spt_init_kernel<<<grid_nk, TPB>>>(node_levels, node_q, NK);
    spt_edge_kernel<<<grid_ek, TPB>>>(node_levels, node_q, edge_rel_q,
                                      edge_w, edge_src, edge_dst, EK);
    spt_final_kernel<<<grid_nk, TPB>>>(out_q, out_l, NK);
}

// round 2
// speedup vs baseline: 1.0213x; 1.0213x over previous
#include <cuda_runtime.h>
#include <cuda_bf16.h>

// Problem constants (fixed by setup_inputs: N=100000, K=8, E=3200000)
#define KDIM 8

static const int MAXN  = 100000;
static const int MAXNK = MAXN * KDIM;

// Scratch accumulators (device globals — no cudaMalloc allowed).
// g_accQ4[i]  = sum over in-edges of exp_e * accu_q   (float4: w,x,y,z)
// g_accDL2[i] = { sum exp_e , sum exp_e * l_src }
__device__ float4 g_accQ4[MAXNK];
__device__ float2 g_accDL2[MAXNK];

// ---------------------------------------------------------------------------
// Edge scatter. One thread per (edge, k); 8 consecutive threads share one
// edge -> broadcast edge loads, coalesced 128B node_q gathers.
// DL accumulation: lanes pair up (k even grabs k+1's values via shfl) so the
// 8x red.v2 per edge become 4x red.v4  (16 -> 12 RED ops per edge).
// ---------------------------------------------------------------------------
__global__ void spt_edge_kernel(const float*  __restrict__ node_levels,
                                const float4* __restrict__ node_q,
                                const float4* __restrict__ edge_rel_q,
                                const float*  __restrict__ edge_w,
                                const int*    __restrict__ edge_src,
                                const int*    __restrict__ edge_dst,
                                long long EK)
{
    long long t = (long long)blockIdx.x * blockDim.x + threadIdx.x;
    bool active = (t < EK);
    long long tc = active ? t : 0;        // clamp for safe loads
    int e = (int)(tc >> 3);
    int k = (int)(tc & 7);

    int   s  = __ldg(edge_src + e);
    int   d  = __ldg(edge_dst + e);
    float w  = __ldg(edge_w + e);
    float4 rq = __ldg(edge_rel_q + e);

    int si = s * KDIM + k;
    float4 qs = __ldg(node_q + si);
    float  l  = __ldg(node_levels + si);

    float ee  = __expf(8.0f * w * l);     // exp_e (softmax shift omitted; cancels)
    float eel = ee * l;

    // Hamilton product: accu_q = rel_q (*) q_src ; storage order (w,x,y,z)
    float w1 = rq.x, x1 = rq.y, y1 = rq.z, z1 = rq.w;
    float w2 = qs.x, x2 = qs.y, y2 = qs.z, z2 = qs.w;
    float ow = w1*w2 - x1*x2 - y1*y2 - z1*z2;
    float ox = w1*x2 + x1*w2 + y1*z2 - z1*y2;
    float oy = w1*y2 - x1*z2 + y1*w2 + z1*x2;
    float oz = w1*z2 + x1*y2 - y1*x2 + z1*w2;

    int di = d * KDIM + k;

    // Pair up DL values: lane k (even) takes lane k+1's {ee, eel}.
    float nee  = __shfl_down_sync(0xffffffffu, ee, 1);
    float neel = __shfl_down_sync(0xffffffffu, eel, 1);

    if (active) {
        float4* aq = g_accQ4 + di;
        asm volatile("red.global.add.v4.f32 [%0], {%1, %2, %3, %4};"
                     :: "l"(aq), "f"(ee*ow), "f"(ee*ox), "f"(ee*oy), "f"(ee*oz)
                     : "memory");
        if ((k & 1) == 0) {
            // covers {d_k, l_k, d_{k+1}, l_{k+1}} : 16B aligned since di even
            float4* adl = (float4*)(g_accDL2 + di);
            asm volatile("red.global.add.v4.f32 [%0], {%1, %2, %3, %4};"
                         :: "l"(adl), "f"(ee), "f"(eel), "f"(nee), "f"(neel)
                         : "memory");
        }
    }
}

// ---------------------------------------------------------------------------
// Finalize: add self term (w=1 -> score 8*l), divide by denom, L2-normalize.
// ---------------------------------------------------------------------------
__global__ void spt_final_kernel(const float* __restrict__ node_levels,
                                 const float4* __restrict__ node_q,
                                 float4* __restrict__ out_q,
                                 float*  __restrict__ out_l,
                                 int NK)
{
    int i = blockIdx.x * blockDim.x + threadIdx.x;
    if (i >= NK) return;

    float  l  = node_levels[i];
    float  es = __expf(8.0f * l);         // self term exp
    float4 q  = node_q[i];

    float2 dl = g_accDL2[i];
    float denom = dl.x + es;
    float suml  = dl.y + es * l;

    float4 a = g_accQ4[i];
    float qw = a.x + es * q.x;
    float qx = a.y + es * q.y;
    float qy = a.z + es * q.z;
    float qz = a.w + es * q.w;

    float inv = 1.0f / denom;
    qw *= inv; qx *= inv; qy *= inv; qz *= inv;

    float nrm = sqrtf(qw*qw + qx*qx + qy*qy + qz*qz);
    float r   = 1.0f / fmaxf(nrm, 1e-12f);
    out_q[i] = make_float4(qw * r, qx * r, qy * r, qz * r);
    out_l[i] = suml * inv;
}

// ---------------------------------------------------------------------------
// Launch: inputs in metadata order:
//   0 node_levels [N,K] f32, 1 node_q [N,K,4] f32, 2 edge_rel_q [E,4] f32,
//   3 edge_w [E] f32, 4 edge_src [E] i32, 5 edge_dst [E] i32
// Output: q [N,K,4] flattened, then out_levels [N,K].
// ---------------------------------------------------------------------------
extern "C" void kernel_launch(void* const* d_in, const int* in_sizes, int n_in,
                              void* d_out, int out_size)
{
    const float*  node_levels = (const float*) d_in[0];
    const float4* node_q      = (const float4*)d_in[1];
    const float4* edge_rel_q  = (const float4*)d_in[2];
    const float*  edge_w      = (const float*) d_in[3];
    const int*    edge_src    = (const int*)   d_in[4];
    const int*    edge_dst    = (const int*)   d_in[5];

    int NK = in_sizes[0];                 // N*K
    int E  = in_sizes[3];
    long long EK = (long long)E * KDIM;

    float4* out_q = (float4*)d_out;
    float*  out_l = (float*)d_out + (long long)NK * 4;

    // Zero the accumulators (graph-capturable async memsets, no read pass).
    void* pQ = nullptr; void* pDL = nullptr;
    cudaGetSymbolAddress(&pQ,  g_accQ4);
    cudaGetSymbolAddress(&pDL, g_accDL2);
    cudaMemsetAsync(pQ,  0, (size_t)NK * sizeof(float4), 0);
    cudaMemsetAsync(pDL, 0, (size_t)NK * sizeof(float2), 0);

    const int TPB = 256;
    int grid_nk = (NK + TPB - 1) / TPB;
    int grid_ek = (int)((EK + TPB - 1) / TPB);

    spt_edge_kernel<<<grid_ek, TPB>>>(node_levels, node_q, edge_rel_q,
                                      edge_w, edge_src, edge_dst, EK);
    spt_final_kernel<<<grid_nk, TPB>>>(node_levels, node_q, out_q, out_l, NK);
}